// round 2
// baseline (speedup 1.0000x reference)
#include <cuda_runtime.h>
#include <cstdint>

#define N_BATCH 256
#define C_DIM   2048
#define HW      49
#define CH      128                  // c-rows per staged chunk
#define NCHUNK  (C_DIM / CH)         // 16
#define ELEMS   (CH * HW)            // 6272 floats per chunk (contiguous in x[n])
#define SMEM_FLOATS (4 * C_DIM + 2 * ELEMS)   // wpack(float4*2048=8192f) + 2 x-buffers
#define SMEM_BYTES  (SMEM_FLOATS * 4)         // 82944 B

// Scratch (device globals, no allocation)
__device__ float g_S [N_BATCH][HW];
__device__ float g_D0[N_BATCH][HW];
__device__ float g_D1[N_BATCH][HW];
__device__ float g_A0[N_BATCH][HW];
__device__ float g_A1[N_BATCH][HW];

__device__ __forceinline__ void cp_async16(uint32_t smem_addr, const void* gptr) {
    asm volatile("cp.async.cg.shared.global [%0], [%1], 16;\n" :: "r"(smem_addr), "l"(gptr));
}
__device__ __forceinline__ void cp_async_commit() {
    asm volatile("cp.async.commit_group;\n" ::: "memory");
}
template <int N> __device__ __forceinline__ void cp_async_wait() {
    asm volatile("cp.async.wait_group %0;\n" :: "n"(N) : "memory");
}

// Kernel 1: per (n,p) compute 5 dot-products over C in one pass over x.
__global__ void __launch_bounds__(256, 2)
rcp_reduce_kernel(const float* __restrict__ x, const float* __restrict__ W) {
    const int n    = blockIdx.x;
    const int tid  = threadIdx.x;
    const int wid  = tid >> 5;
    const int lane = tid & 31;

    extern __shared__ float smem[];
    float4* wpack = reinterpret_cast<float4*>(smem);   // [C_DIM]
    float*  xs    = smem + 4 * C_DIM;                  // 2 buffers of ELEMS

    // Stage W packed: {A0w, A1w, D0w, D1w} per c.
    // W layout (2, 4096): W[o*4096 + c] first half (max_features), W[o*4096+2048+c] second half.
    for (int c = tid; c < C_DIM; c += 256) {
        wpack[c] = make_float4(W[c], W[4096 + c], W[2048 + c], W[6144 + c]);
    }

    const float* xn = x + (size_t)n * (C_DIM * HW);

    // Prefetch chunk 0
    {
        const float4* src = reinterpret_cast<const float4*>(xn);
        for (int i = tid; i < ELEMS / 4; i += 256)
            cp_async16((uint32_t)__cvta_generic_to_shared(xs + 4 * i), src + i);
        cp_async_commit();
    }

    float s[7]  = {0,0,0,0,0,0,0};
    float a0[7] = {0,0,0,0,0,0,0};
    float a1[7] = {0,0,0,0,0,0,0};
    float d0[7] = {0,0,0,0,0,0,0};
    float d1[7] = {0,0,0,0,0,0,0};

    for (int chunk = 0; chunk < NCHUNK; chunk++) {
        // Prefetch next chunk into the other buffer
        if (chunk + 1 < NCHUNK) {
            const float4* src = reinterpret_cast<const float4*>(xn + (chunk + 1) * ELEMS);
            float* dst = xs + ((chunk + 1) & 1) * ELEMS;
            for (int i = tid; i < ELEMS / 4; i += 256)
                cp_async16((uint32_t)__cvta_generic_to_shared(dst + 4 * i), src + i);
            cp_async_commit();
            cp_async_wait<1>();
        } else {
            cp_async_wait<0>();
        }
        __syncthreads();

        const float*  xb = xs + (chunk & 1) * ELEMS;
        const float4* wp = wpack + chunk * CH;

        for (int cl = lane; cl < CH; cl += 32) {
            float4 w = wp[cl];
            const float* row = xb + cl * HW;
            #pragma unroll
            for (int i = 0; i < 7; i++) {
                int p = wid + 8 * i;
                if (p < HW) {
                    float xv = row[p];
                    s[i]  += xv;
                    a0[i]  = fmaf(xv, w.x, a0[i]);
                    a1[i]  = fmaf(xv, w.y, a1[i]);
                    d0[i]  = fmaf(xv, w.z, d0[i]);
                    d1[i]  = fmaf(xv, w.w, d1[i]);
                }
            }
        }
        __syncthreads();   // protect buffer reuse (chunk&1 reloaded at chunk+2)
    }

    // Warp-level reduction of each accumulator, lane 0 writes scratch.
    #pragma unroll
    for (int i = 0; i < 7; i++) {
        int p = wid + 8 * i;
        float vs = s[i], u0 = a0[i], u1 = a1[i], v0 = d0[i], v1 = d1[i];
        #pragma unroll
        for (int off = 16; off; off >>= 1) {
            vs += __shfl_xor_sync(0xFFFFFFFFu, vs, off);
            u0 += __shfl_xor_sync(0xFFFFFFFFu, u0, off);
            u1 += __shfl_xor_sync(0xFFFFFFFFu, u1, off);
            v0 += __shfl_xor_sync(0xFFFFFFFFu, v0, off);
            v1 += __shfl_xor_sync(0xFFFFFFFFu, v1, off);
        }
        if (lane == 0 && p < HW) {
            g_S [n][p] = vs;
            g_A0[n][p] = u0;
            g_A1[n][p] = u1;
            g_D0[n][p] = v0;
            g_D1[n][p] = v1;
        }
    }
}

// Kernel 2: per-n epilogue (threshold, argmax, relu, geometry, gap-mean, loss).
__global__ void __launch_bounds__(32)
rcp_epilogue_kernel(const float* __restrict__ mask, const float* __restrict__ bvec,
                    float* __restrict__ out) {
    const int n    = blockIdx.x;
    const int lane = threadIdx.x;
    const float* m = mask + n * HW;

    // threshold = mean(mask)
    float m0 = m[lane];                                   // lane < 32 <= 49, always valid
    float m1 = (lane + 32 < HW) ? m[lane + 32] : 0.0f;
    float msum = m0 + m1;
    #pragma unroll
    for (int off = 16; off; off >>= 1) msum += __shfl_xor_sync(0xFFFFFFFFu, msum, off);
    const float thr = msum * (1.0f / 49.0f);

    // masked mean + argmax (first-index tie-break, matching jnp.argmax)
    float v0 = (m0 > thr) ? g_S[n][lane] * (1.0f / (float)C_DIM) : 0.0f;
    float bv = v0;
    int   bi = lane;
    if (lane + 32 < HW) {
        float v1 = (m1 > thr) ? g_S[n][lane + 32] * (1.0f / (float)C_DIM) : 0.0f;
        if (v1 > bv) { bv = v1; bi = lane + 32; }         // tie keeps smaller index
    }
    #pragma unroll
    for (int off = 16; off; off >>= 1) {
        float ov = __shfl_xor_sync(0xFFFFFFFFu, bv, off);
        int   oi = __shfl_xor_sync(0xFFFFFFFFu, bi, off);
        if (ov > bv || (ov == bv && oi < bi)) { bv = ov; bi = oi; }
    }
    const int pstar = bi;

    const float A0s = g_A0[n][pstar];
    const float A1s = g_A1[n][pstar];
    const float b0 = bvec[0], b1 = bvec[1];
    const float ai = (float)(pstar / 7);
    const float aj = (float)(pstar % 7);
    const float inv_pi = 0.318309886183790672f;

    float dist[2], gap[2];
    float gsum = 0.0f;
    #pragma unroll
    for (int t = 0; t < 2; t++) {
        int p = lane + 32 * t;
        if (p < HW) {
            float pd = fmaxf(A0s + g_D0[n][p] + b0, 0.0f);
            float pa = fmaxf(A1s + g_D1[n][p] + b1, 0.0f);
            if (p == pstar) { pd = 0.0f; pa = 0.0f; }
            float ri = ((float)(p / 7) - ai) * (1.0f / 7.0f);
            float rj = ((float)(p % 7) - aj) * (1.0f / 7.0f);
            float rd = sqrtf(ri * ri + rj * rj);
            float ra = (atan2f(rj, ri) * inv_pi + 1.0f) * 0.5f;
            float g  = pa - ra;
            if (g < 0.0f) g += 1.0f;
            float dl = pd - rd;
            dist[t] = dl * dl;
            gap[t]  = g;
            gsum   += g;
        } else {
            dist[t] = 0.0f; gap[t] = 0.0f;
        }
    }
    #pragma unroll
    for (int off = 16; off; off >>= 1) gsum += __shfl_xor_sync(0xFFFFFFFFu, gsum, off);
    const float gmean = gsum * (1.0f / 49.0f);

    #pragma unroll
    for (int t = 0; t < 2; t++) {
        int p = lane + 32 * t;
        if (p < HW) {
            float gg = gap[t] - gmean;
            out[n * HW + p] = dist[t] + gg * gg;
        }
    }
}

extern "C" void kernel_launch(void* const* d_in, const int* in_sizes, int n_in,
                              void* d_out, int out_size) {
    const float* x    = (const float*)d_in[0];   // (256, 2048, 7, 7)
    const float* mask = (const float*)d_in[1];   // (256, 7, 7)
    const float* W    = (const float*)d_in[2];   // (2, 4096)
    const float* b    = (const float*)d_in[3];   // (2,)
    float* out = (float*)d_out;                  // (256, 7, 7)

    cudaFuncSetAttribute(rcp_reduce_kernel,
                         cudaFuncAttributeMaxDynamicSharedMemorySize, SMEM_BYTES);

    rcp_reduce_kernel<<<N_BATCH, 256, SMEM_BYTES>>>(x, W);
    rcp_epilogue_kernel<<<N_BATCH, 32>>>(mask, b, out);
}

// round 3
// speedup vs baseline: 1.2208x; 1.2208x over previous
#include <cuda_runtime.h>
#include <cstdint>

#define N_BATCH 256
#define C_DIM   2048
#define HW      49
#define CH      64                   // c-rows per staged chunk
#define NCHUNK  (C_DIM / CH)         // 32
#define ELEMS   (CH * HW)            // 3136 floats per chunk (contiguous in x[n])
#define NBUF    4
#define SMEM_FLOATS (4 * C_DIM + NBUF * ELEMS)   // wpack(8192f) + 4 x-buffers(12544f)
#define SMEM_BYTES  (SMEM_FLOATS * 4)            // 82944 B

__device__ __forceinline__ void cp_async16(uint32_t smem_addr, const void* gptr) {
    asm volatile("cp.async.cg.shared.global [%0], [%1], 16;\n" :: "r"(smem_addr), "l"(gptr));
}
__device__ __forceinline__ void cp_async_commit() {
    asm volatile("cp.async.commit_group;\n" ::: "memory");
}
template <int N> __device__ __forceinline__ void cp_async_wait() {
    asm volatile("cp.async.wait_group %0;\n" :: "n"(N) : "memory");
}

// One CTA per batch n: 5 dot-products over C per p (single pass over x),
// then fused per-n epilogue (threshold, argmax, relu, geometry, gap-mean, loss).
__global__ void __launch_bounds__(256, 2)
rcp_fused_kernel(const float* __restrict__ x, const float* __restrict__ mask,
                 const float* __restrict__ W, const float* __restrict__ bvec,
                 float* __restrict__ out) {
    const int n    = blockIdx.x;
    const int tid  = threadIdx.x;
    const int wid  = tid >> 5;
    const int lane = tid & 31;

    extern __shared__ float smem[];
    float4* wpack = reinterpret_cast<float4*>(smem);   // [C_DIM] float4
    float*  xs    = smem + 4 * C_DIM;                  // NBUF buffers of ELEMS

    // Stage W packed: {A0w, A1w, D0w, D1w} per c.
    // W layout (2, 4096): W[o*4096 + c] first half (max_features), W[o*4096+2048+c] second half.
    for (int c = tid; c < C_DIM; c += 256) {
        wpack[c] = make_float4(W[c], W[4096 + c], W[2048 + c], W[6144 + c]);
    }

    const float* xn = x + (size_t)n * (C_DIM * HW);

    // Prefetch chunks 0..2 (three committed groups)
    #pragma unroll
    for (int pc = 0; pc < 3; pc++) {
        const float4* src = reinterpret_cast<const float4*>(xn + pc * ELEMS);
        float* dst = xs + pc * ELEMS;
        for (int i = tid; i < ELEMS / 4; i += 256)
            cp_async16((uint32_t)__cvta_generic_to_shared(dst + 4 * i), src + i);
        cp_async_commit();
    }

    float s[7]  = {0,0,0,0,0,0,0};
    float a0[7] = {0,0,0,0,0,0,0};
    float a1[7] = {0,0,0,0,0,0,0};
    float d0[7] = {0,0,0,0,0,0,0};
    float d1[7] = {0,0,0,0,0,0,0};

    for (int chunk = 0; chunk < NCHUNK; chunk++) {
        cp_async_wait<2>();          // chunk's group complete (3 outstanding max)
        __syncthreads();             // make buffer visible to all warps; also
                                     // guarantees buffer (chunk+3)&3 is free

        // Issue prefetch for chunk+3 (always commit to keep group counts aligned)
        if (chunk + 3 < NCHUNK) {
            const float4* src = reinterpret_cast<const float4*>(xn + (chunk + 3) * ELEMS);
            float* dst = xs + ((chunk + 3) & (NBUF - 1)) * ELEMS;
            for (int i = tid; i < ELEMS / 4; i += 256)
                cp_async16((uint32_t)__cvta_generic_to_shared(dst + 4 * i), src + i);
        }
        cp_async_commit();

        const float*  xb = xs + (chunk & (NBUF - 1)) * ELEMS;
        const float4* wp = wpack + chunk * CH;

        #pragma unroll
        for (int it = 0; it < 2; it++) {
            const int cl = lane + 32 * it;
            float4 w = wp[cl];
            const float* row = xb + cl * HW;
            #pragma unroll
            for (int i = 0; i < 7; i++) {
                int p = wid + 8 * i;
                if (p < HW) {
                    float xv = row[p];
                    s[i]  += xv;
                    a0[i]  = fmaf(xv, w.x, a0[i]);
                    a1[i]  = fmaf(xv, w.y, a1[i]);
                    d0[i]  = fmaf(xv, w.z, d0[i]);
                    d1[i]  = fmaf(xv, w.w, d1[i]);
                }
            }
        }
    }

    // Warp-level reduction; results to SMEM (reuse wpack region — chunk-0 W
    // values there were last read 31 chunks ago and all warps are past it,
    // but sync anyway for safety).
    float* rS  = smem;
    float* rA0 = smem + HW;
    float* rA1 = smem + 2 * HW;
    float* rD0 = smem + 3 * HW;
    float* rD1 = smem + 4 * HW;

    __syncthreads();
    #pragma unroll
    for (int i = 0; i < 7; i++) {
        int p = wid + 8 * i;
        float vs = s[i], u0 = a0[i], u1 = a1[i], v0 = d0[i], v1 = d1[i];
        #pragma unroll
        for (int off = 16; off; off >>= 1) {
            vs += __shfl_xor_sync(0xFFFFFFFFu, vs, off);
            u0 += __shfl_xor_sync(0xFFFFFFFFu, u0, off);
            u1 += __shfl_xor_sync(0xFFFFFFFFu, u1, off);
            v0 += __shfl_xor_sync(0xFFFFFFFFu, v0, off);
            v1 += __shfl_xor_sync(0xFFFFFFFFu, v1, off);
        }
        if (lane == 0 && p < HW) {
            rS [p] = vs;
            rA0[p] = u0;
            rA1[p] = u1;
            rD0[p] = v0;
            rD1[p] = v1;
        }
    }
    __syncthreads();

    // ---- Fused epilogue: warp 0 only ----
    if (wid == 0) {
        const float* m = mask + n * HW;

        // threshold = mean(mask)
        float m0 = m[lane];                                   // lane < 32 <= 49
        float m1 = (lane + 32 < HW) ? m[lane + 32] : 0.0f;
        float msum = m0 + m1;
        #pragma unroll
        for (int off = 16; off; off >>= 1) msum += __shfl_xor_sync(0xFFFFFFFFu, msum, off);
        const float thr = msum * (1.0f / 49.0f);

        // masked mean + argmax (first-index tie-break, matching jnp.argmax)
        float v0 = (m0 > thr) ? rS[lane] * (1.0f / (float)C_DIM) : 0.0f;
        float bv = v0;
        int   bi = lane;
        if (lane + 32 < HW) {
            float v1 = (m1 > thr) ? rS[lane + 32] * (1.0f / (float)C_DIM) : 0.0f;
            if (v1 > bv) { bv = v1; bi = lane + 32; }         // tie keeps smaller index
        }
        #pragma unroll
        for (int off = 16; off; off >>= 1) {
            float ov = __shfl_xor_sync(0xFFFFFFFFu, bv, off);
            int   oi = __shfl_xor_sync(0xFFFFFFFFu, bi, off);
            if (ov > bv || (ov == bv && oi < bi)) { bv = ov; bi = oi; }
        }
        const int pstar = bi;

        const float A0s = rA0[pstar];
        const float A1s = rA1[pstar];
        const float b0 = bvec[0], b1 = bvec[1];
        const float ai = (float)(pstar / 7);
        const float aj = (float)(pstar % 7);
        const float inv_pi = 0.318309886183790672f;

        float dist[2], gap[2];
        float gsum = 0.0f;
        #pragma unroll
        for (int t = 0; t < 2; t++) {
            int p = lane + 32 * t;
            if (p < HW) {
                float pd = fmaxf(A0s + rD0[p] + b0, 0.0f);
                float pa = fmaxf(A1s + rD1[p] + b1, 0.0f);
                if (p == pstar) { pd = 0.0f; pa = 0.0f; }
                float ri = ((float)(p / 7) - ai) * (1.0f / 7.0f);
                float rj = ((float)(p % 7) - aj) * (1.0f / 7.0f);
                float rd = sqrtf(ri * ri + rj * rj);
                float ra = (atan2f(rj, ri) * inv_pi + 1.0f) * 0.5f;
                float g  = pa - ra;
                if (g < 0.0f) g += 1.0f;
                float dl = pd - rd;
                dist[t] = dl * dl;
                gap[t]  = g;
                gsum   += g;
            } else {
                dist[t] = 0.0f; gap[t] = 0.0f;
            }
        }
        #pragma unroll
        for (int off = 16; off; off >>= 1) gsum += __shfl_xor_sync(0xFFFFFFFFu, gsum, off);
        const float gmean = gsum * (1.0f / 49.0f);

        #pragma unroll
        for (int t = 0; t < 2; t++) {
            int p = lane + 32 * t;
            if (p < HW) {
                float gg = gap[t] - gmean;
                out[n * HW + p] = dist[t] + gg * gg;
            }
        }
    }
}

extern "C" void kernel_launch(void* const* d_in, const int* in_sizes, int n_in,
                              void* d_out, int out_size) {
    const float* x    = (const float*)d_in[0];   // (256, 2048, 7, 7)
    const float* mask = (const float*)d_in[1];   // (256, 7, 7)
    const float* W    = (const float*)d_in[2];   // (2, 4096)
    const float* b    = (const float*)d_in[3];   // (2,)
    float* out = (float*)d_out;                  // (256, 7, 7)

    cudaFuncSetAttribute(rcp_fused_kernel,
                         cudaFuncAttributeMaxDynamicSharedMemorySize, SMEM_BYTES);

    rcp_fused_kernel<<<N_BATCH, 256, SMEM_BYTES>>>(x, mask, W, b, out);
}

// round 4
// speedup vs baseline: 1.3269x; 1.0869x over previous
#include <cuda_runtime.h>
#include <cstdint>

#define N_BATCH 256
#define C_DIM   2048
#define HW      49
#define CH      128                  // c-rows per staged chunk
#define NCHUNK  (C_DIM / CH)         // 16
#define ELEMS   (CH * HW)            // 6272 floats per chunk (contiguous in x[n])
#define CHUNK_BYTES (ELEMS * 4)      // 25088 B, multiple of 16
#define NBUF    3
// smem: mbar[NBUF] (8B each, padded to 32 floats) + wpack (float4[C_DIM]) + NBUF x-buffers
#define SMEM_MBAR_FLOATS 32
#define SMEM_FLOATS (SMEM_MBAR_FLOATS + 4 * C_DIM + NBUF * ELEMS)
#define SMEM_BYTES  (SMEM_FLOATS * 4)   // 128 + 32768 + 75264 = 108160 B

__device__ __forceinline__ uint32_t smem_u32(const void* p) {
    return (uint32_t)__cvta_generic_to_shared(p);
}
__device__ __forceinline__ void mbar_init(uint32_t mbar, uint32_t count) {
    asm volatile("mbarrier.init.shared::cta.b64 [%0], %1;" :: "r"(mbar), "r"(count) : "memory");
}
__device__ __forceinline__ void mbar_expect_tx(uint32_t mbar, uint32_t bytes) {
    asm volatile("mbarrier.arrive.expect_tx.shared::cta.b64 _, [%0], %1;"
                 :: "r"(mbar), "r"(bytes) : "memory");
}
__device__ __forceinline__ void bulk_g2s(uint32_t smem_dst, const void* gsrc,
                                         uint32_t bytes, uint32_t mbar) {
    asm volatile("cp.async.bulk.shared::cta.global.mbarrier::complete_tx::bytes "
                 "[%0], [%1], %2, [%3];"
                 :: "r"(smem_dst), "l"(gsrc), "r"(bytes), "r"(mbar) : "memory");
}
__device__ __forceinline__ void mbar_wait(uint32_t mbar, uint32_t parity) {
    uint32_t done;
    asm volatile(
        "{\n\t.reg .pred p;\n\t"
        "mbarrier.try_wait.parity.acquire.cta.shared::cta.b64 p, [%1], %2;\n\t"
        "selp.b32 %0, 1, 0, p;\n\t}"
        : "=r"(done) : "r"(mbar), "r"(parity) : "memory");
    if (!done) {
        asm volatile(
            "{\n\t.reg .pred P1;\n\t"
            "WAIT_LOOP_%=:\n\t"
            "mbarrier.try_wait.parity.acquire.cta.shared::cta.b64 P1, [%0], %1, 0x989680;\n\t"
            "@P1 bra.uni WAIT_DONE_%=;\n\t"
            "bra.uni WAIT_LOOP_%=;\n\t"
            "WAIT_DONE_%=:\n\t}"
            :: "r"(mbar), "r"(parity) : "memory");
    }
}

// One CTA per batch n: 5 dot-products over C per p (single pass over x),
// then fused per-n epilogue (threshold, argmax, relu, geometry, gap-mean, loss).
__global__ void __launch_bounds__(256, 2)
rcp_fused_kernel(const float* __restrict__ x, const float* __restrict__ mask,
                 const float* __restrict__ W, const float* __restrict__ bvec,
                 float* __restrict__ out) {
    const int n    = blockIdx.x;
    const int tid  = threadIdx.x;
    const int wid  = tid >> 5;
    const int lane = tid & 31;

    extern __shared__ float smem[];
    uint64_t* mbar_s = reinterpret_cast<uint64_t*>(smem);            // [NBUF]
    float4*   wpack  = reinterpret_cast<float4*>(smem + SMEM_MBAR_FLOATS); // [C_DIM]
    float*    xs     = smem + SMEM_MBAR_FLOATS + 4 * C_DIM;          // NBUF x ELEMS

    const uint32_t mbar0 = smem_u32(&mbar_s[0]);

    if (tid == 0) {
        #pragma unroll
        for (int b = 0; b < NBUF; b++) mbar_init(mbar0 + 8 * b, 1);
    }

    // Stage W packed: {A0w, A1w, D0w, D1w} per c.
    // W layout (2, 4096): W[o*4096 + c] first half (max_features), W[o*4096+2048+c] second.
    for (int c = tid; c < C_DIM; c += 256) {
        wpack[c] = make_float4(W[c], W[4096 + c], W[2048 + c], W[6144 + c]);
    }

    const float* xn = x + (size_t)n * (C_DIM * HW);

    __syncthreads();   // mbarrier init visible before first bulk issue

    // Prefetch chunks 0..NBUF-1 via single-thread bulk copies
    if (tid == 0) {
        #pragma unroll
        for (int pc = 0; pc < NBUF; pc++) {
            uint32_t mb = mbar0 + 8 * pc;
            mbar_expect_tx(mb, CHUNK_BYTES);
            bulk_g2s(smem_u32(xs + pc * ELEMS), xn + pc * ELEMS, CHUNK_BYTES, mb);
        }
    }

    float s[7]  = {0,0,0,0,0,0,0};
    float a0[7] = {0,0,0,0,0,0,0};
    float a1[7] = {0,0,0,0,0,0,0};
    float d0[7] = {0,0,0,0,0,0,0};
    float d1[7] = {0,0,0,0,0,0,0};

    int buf = 0, phase = 0;
    for (int chunk = 0; chunk < NCHUNK; chunk++) {
        mbar_wait(mbar0 + 8 * buf, phase);

        const float*  xb = xs + buf * ELEMS;
        const float4* wp = wpack + chunk * CH;

        #pragma unroll
        for (int it = 0; it < 4; it++) {
            const int cl = lane + 32 * it;
            float4 w = wp[cl];
            const float* row = xb + cl * HW;
            #pragma unroll
            for (int i = 0; i < 7; i++) {
                int p = wid + 8 * i;
                if (p < HW) {
                    float xv = row[p];
                    s[i]  += xv;
                    a0[i]  = fmaf(xv, w.x, a0[i]);
                    a1[i]  = fmaf(xv, w.y, a1[i]);
                    d0[i]  = fmaf(xv, w.z, d0[i]);
                    d1[i]  = fmaf(xv, w.w, d1[i]);
                }
            }
        }

        __syncthreads();   // everyone done reading this buffer

        // Refill this buffer with chunk+NBUF
        if (tid == 0 && chunk + NBUF < NCHUNK) {
            uint32_t mb = mbar0 + 8 * buf;
            mbar_expect_tx(mb, CHUNK_BYTES);
            bulk_g2s(smem_u32(xs + buf * ELEMS), xn + (chunk + NBUF) * ELEMS,
                     CHUNK_BYTES, mb);
        }

        if (++buf == NBUF) { buf = 0; phase ^= 1; }
    }

    // Warp-level reduction; results to SMEM (wpack region is dead now).
    float* rS  = smem + SMEM_MBAR_FLOATS;
    float* rA0 = rS + HW;
    float* rA1 = rS + 2 * HW;
    float* rD0 = rS + 3 * HW;
    float* rD1 = rS + 4 * HW;

    __syncthreads();
    #pragma unroll
    for (int i = 0; i < 7; i++) {
        int p = wid + 8 * i;
        float vs = s[i], u0 = a0[i], u1 = a1[i], v0 = d0[i], v1 = d1[i];
        #pragma unroll
        for (int off = 16; off; off >>= 1) {
            vs += __shfl_xor_sync(0xFFFFFFFFu, vs, off);
            u0 += __shfl_xor_sync(0xFFFFFFFFu, u0, off);
            u1 += __shfl_xor_sync(0xFFFFFFFFu, u1, off);
            v0 += __shfl_xor_sync(0xFFFFFFFFu, v0, off);
            v1 += __shfl_xor_sync(0xFFFFFFFFu, v1, off);
        }
        if (lane == 0 && p < HW) {
            rS [p] = vs;
            rA0[p] = u0;
            rA1[p] = u1;
            rD0[p] = v0;
            rD1[p] = v1;
        }
    }
    __syncthreads();

    // ---- Fused epilogue: warp 0 only ----
    if (wid == 0) {
        const float* m = mask + n * HW;

        // threshold = mean(mask)
        float m0 = m[lane];                                   // lane < 32 <= 49
        float m1 = (lane + 32 < HW) ? m[lane + 32] : 0.0f;
        float msum = m0 + m1;
        #pragma unroll
        for (int off = 16; off; off >>= 1) msum += __shfl_xor_sync(0xFFFFFFFFu, msum, off);
        const float thr = msum * (1.0f / 49.0f);

        // masked mean + argmax (first-index tie-break, matching jnp.argmax)
        float v0 = (m0 > thr) ? rS[lane] * (1.0f / (float)C_DIM) : 0.0f;
        float bv = v0;
        int   bi = lane;
        if (lane + 32 < HW) {
            float v1 = (m1 > thr) ? rS[lane + 32] * (1.0f / (float)C_DIM) : 0.0f;
            if (v1 > bv) { bv = v1; bi = lane + 32; }         // tie keeps smaller index
        }
        #pragma unroll
        for (int off = 16; off; off >>= 1) {
            float ov = __shfl_xor_sync(0xFFFFFFFFu, bv, off);
            int   oi = __shfl_xor_sync(0xFFFFFFFFu, bi, off);
            if (ov > bv || (ov == bv && oi < bi)) { bv = ov; bi = oi; }
        }
        const int pstar = bi;

        const float A0s = rA0[pstar];
        const float A1s = rA1[pstar];
        const float b0 = bvec[0], b1 = bvec[1];
        const float ai = (float)(pstar / 7);
        const float aj = (float)(pstar % 7);
        const float inv_pi = 0.318309886183790672f;

        float dist[2], gap[2];
        float gsum = 0.0f;
        #pragma unroll
        for (int t = 0; t < 2; t++) {
            int p = lane + 32 * t;
            if (p < HW) {
                float pd = fmaxf(A0s + rD0[p] + b0, 0.0f);
                float pa = fmaxf(A1s + rD1[p] + b1, 0.0f);
                if (p == pstar) { pd = 0.0f; pa = 0.0f; }
                float ri = ((float)(p / 7) - ai) * (1.0f / 7.0f);
                float rj = ((float)(p % 7) - aj) * (1.0f / 7.0f);
                float rd = sqrtf(ri * ri + rj * rj);
                float ra = (atan2f(rj, ri) * inv_pi + 1.0f) * 0.5f;
                float g  = pa - ra;
                if (g < 0.0f) g += 1.0f;
                float dl = pd - rd;
                dist[t] = dl * dl;
                gap[t]  = g;
                gsum   += g;
            } else {
                dist[t] = 0.0f; gap[t] = 0.0f;
            }
        }
        #pragma unroll
        for (int off = 16; off; off >>= 1) gsum += __shfl_xor_sync(0xFFFFFFFFu, gsum, off);
        const float gmean = gsum * (1.0f / 49.0f);

        #pragma unroll
        for (int t = 0; t < 2; t++) {
            int p = lane + 32 * t;
            if (p < HW) {
                float gg = gap[t] - gmean;
                out[n * HW + p] = dist[t] + gg * gg;
            }
        }
    }
}

extern "C" void kernel_launch(void* const* d_in, const int* in_sizes, int n_in,
                              void* d_out, int out_size) {
    const float* x    = (const float*)d_in[0];   // (256, 2048, 7, 7)
    const float* mask = (const float*)d_in[1];   // (256, 7, 7)
    const float* W    = (const float*)d_in[2];   // (2, 4096)
    const float* b    = (const float*)d_in[3];   // (2,)
    float* out = (float*)d_out;                  // (256, 7, 7)

    cudaFuncSetAttribute(rcp_fused_kernel,
                         cudaFuncAttributeMaxDynamicSharedMemorySize, SMEM_BYTES);

    rcp_fused_kernel<<<N_BATCH, 256, SMEM_BYTES>>>(x, mask, W, b, out);
}

// round 5
// speedup vs baseline: 1.3645x; 1.0284x over previous
#include <cuda_runtime.h>
#include <cstdint>

#define N_BATCH 256
#define C_DIM   2048
#define HW      49
#define CH      128                  // c-rows per staged chunk
#define NCHUNK  (C_DIM / CH)         // 16
#define ELEMS   (CH * HW)            // 6272 floats per chunk (contiguous in x[n])
#define CHUNK_BYTES (ELEMS * 4)      // 25088 B, multiple of 16
#define NBUF    3
// smem: mbar[NBUF] (8B each, padded to 32 floats) + wpack (float4[C_DIM]) + NBUF x-buffers
#define SMEM_MBAR_FLOATS 32
#define SMEM_FLOATS (SMEM_MBAR_FLOATS + 4 * C_DIM + NBUF * ELEMS)
#define SMEM_BYTES  (SMEM_FLOATS * 4)   // 128 + 32768 + 75264 = 108160 B

__device__ __forceinline__ uint32_t smem_u32(const void* p) {
    return (uint32_t)__cvta_generic_to_shared(p);
}
__device__ __forceinline__ void mbar_init(uint32_t mbar, uint32_t count) {
    asm volatile("mbarrier.init.shared::cta.b64 [%0], %1;" :: "r"(mbar), "r"(count) : "memory");
}
__device__ __forceinline__ void mbar_expect_tx(uint32_t mbar, uint32_t bytes) {
    asm volatile("mbarrier.arrive.expect_tx.shared::cta.b64 _, [%0], %1;"
                 :: "r"(mbar), "r"(bytes) : "memory");
}
__device__ __forceinline__ void bulk_g2s(uint32_t smem_dst, const void* gsrc,
                                         uint32_t bytes, uint32_t mbar) {
    asm volatile("cp.async.bulk.shared::cta.global.mbarrier::complete_tx::bytes "
                 "[%0], [%1], %2, [%3];"
                 :: "r"(smem_dst), "l"(gsrc), "r"(bytes), "r"(mbar) : "memory");
}
__device__ __forceinline__ void mbar_wait(uint32_t mbar, uint32_t parity) {
    uint32_t done;
    asm volatile(
        "{\n\t.reg .pred p;\n\t"
        "mbarrier.try_wait.parity.acquire.cta.shared::cta.b64 p, [%1], %2;\n\t"
        "selp.b32 %0, 1, 0, p;\n\t}"
        : "=r"(done) : "r"(mbar), "r"(parity) : "memory");
    if (!done) {
        asm volatile(
            "{\n\t.reg .pred P1;\n\t"
            "WAIT_LOOP_%=:\n\t"
            "mbarrier.try_wait.parity.acquire.cta.shared::cta.b64 P1, [%0], %1, 0x989680;\n\t"
            "@P1 bra.uni WAIT_DONE_%=;\n\t"
            "bra.uni WAIT_LOOP_%=;\n\t"
            "WAIT_DONE_%=:\n\t}"
            :: "r"(mbar), "r"(parity) : "memory");
    }
}

// Packed f32x2 helpers (ptxas never emits FFMA2 from plain C++)
__device__ __forceinline__ void pack_dup(uint64_t& dst, float v) {
    asm("mov.b64 %0, {%1, %1};" : "=l"(dst) : "r"(__float_as_uint(v)));
}
__device__ __forceinline__ void fma2(uint64_t& acc, uint64_t xx, uint64_t ww) {
    asm("fma.rn.f32x2 %0, %1, %2, %0;" : "+l"(acc) : "l"(xx), "l"(ww));
}

// One CTA per batch n: 5 dot-products over C per p (single pass over x),
// then fused per-n epilogue (threshold, argmax, relu, geometry, gap-mean, loss).
__global__ void __launch_bounds__(256, 2)
rcp_fused_kernel(const float* __restrict__ x, const float* __restrict__ mask,
                 const float* __restrict__ W, const float* __restrict__ bvec,
                 float* __restrict__ out) {
    const int n    = blockIdx.x;
    const int tid  = threadIdx.x;
    const int wid  = tid >> 5;
    const int lane = tid & 31;

    extern __shared__ float smem[];
    uint64_t* mbar_s = reinterpret_cast<uint64_t*>(smem);            // [NBUF]
    float4*   wpack  = reinterpret_cast<float4*>(smem + SMEM_MBAR_FLOATS); // [C_DIM]
    float*    xs     = smem + SMEM_MBAR_FLOATS + 4 * C_DIM;          // NBUF x ELEMS

    const uint32_t mbar0 = smem_u32(&mbar_s[0]);

    if (tid == 0) {
        #pragma unroll
        for (int b = 0; b < NBUF; b++) mbar_init(mbar0 + 8 * b, 1);
    }

    // Stage W packed: {A0w, A1w, D0w, D1w} per c.
    // W layout (2, 4096): W[o*4096 + c] first half (max_features), W[o*4096+2048+c] second.
    for (int c = tid; c < C_DIM; c += 256) {
        wpack[c] = make_float4(W[c], W[4096 + c], W[2048 + c], W[6144 + c]);
    }

    const float* xn = x + (size_t)n * (C_DIM * HW);

    __syncthreads();   // mbarrier init visible before first bulk issue

    // Prefetch chunks 0..NBUF-1 via single-thread bulk copies
    if (tid == 0) {
        #pragma unroll
        for (int pc = 0; pc < NBUF; pc++) {
            uint32_t mb = mbar0 + 8 * pc;
            mbar_expect_tx(mb, CHUNK_BYTES);
            bulk_g2s(smem_u32(xs + pc * ELEMS), xn + pc * ELEMS, CHUNK_BYTES, mb);
        }
    }

    float    s[7]    = {0,0,0,0,0,0,0};
    uint64_t accA[7] = {0,0,0,0,0,0,0};   // packed (a0, a1)
    uint64_t accD[7] = {0,0,0,0,0,0,0};   // packed (d0, d1)

    int buf = 0, phase = 0;
    for (int chunk = 0; chunk < NCHUNK; chunk++) {
        mbar_wait(mbar0 + 8 * buf, phase);

        const float*     xb  = xs + buf * ELEMS;
        const ulonglong2* wp2 = reinterpret_cast<const ulonglong2*>(wpack + chunk * CH);

        #pragma unroll
        for (int it = 0; it < 4; it++) {
            const int cl = lane + 32 * it;
            ulonglong2 w2 = wp2[cl];            // LDS.128: wA={A0w,A1w}, wD={D0w,D1w}
            const float* row = xb + cl * HW;

            // p = wid + 8*i; for i<=5, p <= 7+40=47 < 49: always in-bounds.
            float xv[6];
            #pragma unroll
            for (int i = 0; i < 6; i++) xv[i] = row[wid + 8 * i];

            #pragma unroll
            for (int i = 0; i < 6; i++) {
                uint64_t xx; pack_dup(xx, xv[i]);
                s[i] += xv[i];
                fma2(accA[i], xx, w2.x);
                fma2(accD[i], xx, w2.y);
            }
            if (wid == 0) {                     // i=6 -> p=48 only valid for wid 0
                float x6 = row[48];
                uint64_t xx; pack_dup(xx, x6);
                s[6] += x6;
                fma2(accA[6], xx, w2.x);
                fma2(accD[6], xx, w2.y);
            }
        }

        __syncthreads();   // everyone done reading this buffer

        // Refill this buffer with chunk+NBUF
        if (tid == 0 && chunk + NBUF < NCHUNK) {
            uint32_t mb = mbar0 + 8 * buf;
            mbar_expect_tx(mb, CHUNK_BYTES);
            bulk_g2s(smem_u32(xs + buf * ELEMS), xn + (chunk + NBUF) * ELEMS,
                     CHUNK_BYTES, mb);
        }

        if (++buf == NBUF) { buf = 0; phase ^= 1; }
    }

    // Warp-level reduction; results to SMEM (wpack region is dead now).
    float* rS  = smem + SMEM_MBAR_FLOATS;
    float* rA0 = rS + HW;
    float* rA1 = rS + 2 * HW;
    float* rD0 = rS + 3 * HW;
    float* rD1 = rS + 4 * HW;

    __syncthreads();
    #pragma unroll
    for (int i = 0; i < 7; i++) {
        int p = wid + 8 * i;
        float vs = s[i];
        float u0 = __uint_as_float((uint32_t)(accA[i] & 0xFFFFFFFFu));
        float u1 = __uint_as_float((uint32_t)(accA[i] >> 32));
        float v0 = __uint_as_float((uint32_t)(accD[i] & 0xFFFFFFFFu));
        float v1 = __uint_as_float((uint32_t)(accD[i] >> 32));
        #pragma unroll
        for (int off = 16; off; off >>= 1) {
            vs += __shfl_xor_sync(0xFFFFFFFFu, vs, off);
            u0 += __shfl_xor_sync(0xFFFFFFFFu, u0, off);
            u1 += __shfl_xor_sync(0xFFFFFFFFu, u1, off);
            v0 += __shfl_xor_sync(0xFFFFFFFFu, v0, off);
            v1 += __shfl_xor_sync(0xFFFFFFFFu, v1, off);
        }
        if (lane == 0 && p < HW) {
            rS [p] = vs;
            rA0[p] = u0;
            rA1[p] = u1;
            rD0[p] = v0;
            rD1[p] = v1;
        }
    }
    __syncthreads();

    // ---- Fused epilogue: warp 0 only ----
    if (wid == 0) {
        const float* m = mask + n * HW;

        // threshold = mean(mask)
        float m0 = m[lane];                                   // lane < 32 <= 49
        float m1 = (lane + 32 < HW) ? m[lane + 32] : 0.0f;
        float msum = m0 + m1;
        #pragma unroll
        for (int off = 16; off; off >>= 1) msum += __shfl_xor_sync(0xFFFFFFFFu, msum, off);
        const float thr = msum * (1.0f / 49.0f);

        // masked mean + argmax (first-index tie-break, matching jnp.argmax)
        float v0 = (m0 > thr) ? rS[lane] * (1.0f / (float)C_DIM) : 0.0f;
        float bv = v0;
        int   bi = lane;
        if (lane + 32 < HW) {
            float v1 = (m1 > thr) ? rS[lane + 32] * (1.0f / (float)C_DIM) : 0.0f;
            if (v1 > bv) { bv = v1; bi = lane + 32; }         // tie keeps smaller index
        }
        #pragma unroll
        for (int off = 16; off; off >>= 1) {
            float ov = __shfl_xor_sync(0xFFFFFFFFu, bv, off);
            int   oi = __shfl_xor_sync(0xFFFFFFFFu, bi, off);
            if (ov > bv || (ov == bv && oi < bi)) { bv = ov; bi = oi; }
        }
        const int pstar = bi;

        const float A0s = rA0[pstar];
        const float A1s = rA1[pstar];
        const float b0 = bvec[0], b1 = bvec[1];
        const float ai = (float)(pstar / 7);
        const float aj = (float)(pstar % 7);
        const float inv_pi = 0.318309886183790672f;

        float dist[2], gap[2];
        float gsum = 0.0f;
        #pragma unroll
        for (int t = 0; t < 2; t++) {
            int p = lane + 32 * t;
            if (p < HW) {
                float pd = fmaxf(A0s + rD0[p] + b0, 0.0f);
                float pa = fmaxf(A1s + rD1[p] + b1, 0.0f);
                if (p == pstar) { pd = 0.0f; pa = 0.0f; }
                float ri = ((float)(p / 7) - ai) * (1.0f / 7.0f);
                float rj = ((float)(p % 7) - aj) * (1.0f / 7.0f);
                float rd = sqrtf(ri * ri + rj * rj);
                float ra = (atan2f(rj, ri) * inv_pi + 1.0f) * 0.5f;
                float g  = pa - ra;
                if (g < 0.0f) g += 1.0f;
                float dl = pd - rd;
                dist[t] = dl * dl;
                gap[t]  = g;
                gsum   += g;
            } else {
                dist[t] = 0.0f; gap[t] = 0.0f;
            }
        }
        #pragma unroll
        for (int off = 16; off; off >>= 1) gsum += __shfl_xor_sync(0xFFFFFFFFu, gsum, off);
        const float gmean = gsum * (1.0f / 49.0f);

        #pragma unroll
        for (int t = 0; t < 2; t++) {
            int p = lane + 32 * t;
            if (p < HW) {
                float gg = gap[t] - gmean;
                out[n * HW + p] = dist[t] + gg * gg;
            }
        }
    }
}

extern "C" void kernel_launch(void* const* d_in, const int* in_sizes, int n_in,
                              void* d_out, int out_size) {
    const float* x    = (const float*)d_in[0];   // (256, 2048, 7, 7)
    const float* mask = (const float*)d_in[1];   // (256, 7, 7)
    const float* W    = (const float*)d_in[2];   // (2, 4096)
    const float* b    = (const float*)d_in[3];   // (2,)
    float* out = (float*)d_out;                  // (256, 7, 7)

    cudaFuncSetAttribute(rcp_fused_kernel,
                         cudaFuncAttributeMaxDynamicSharedMemorySize, SMEM_BYTES);

    rcp_fused_kernel<<<N_BATCH, 256, SMEM_BYTES>>>(x, mask, W, b, out);
}